// round 14
// baseline (speedup 1.0000x reference)
#include <cuda_runtime.h>
#include <math.h>

#define N_NODES 50000
#define N_EDGES 800000
#define HID 64
#define REL 5

// ---------------- scratch (static __device__, allowed) ----------------
// NOTE: no zero_kernel. g_cnt_row is restored to 0 by scatter (atomicSub matches
// count's atomicAdd exactly); g_cnt_col is reset by scan_dis after reading.
// BSS zero-init covers the first (correctness) run; invariant holds per replay.
__device__ float g_X[N_NODES * HID];            // 12.8 MB (UNscaled x)
__device__ float g_R[N_NODES * REL * HID];      // 64 MB
__device__ int   g_cnt_row[N_NODES];
__device__ int   g_cnt_col[N_NODES];
__device__ int   g_row_ptr[N_NODES + 1];
__device__ unsigned g_pk[N_EDGES];              // packed src | (type<<16)
__device__ float g_dis[N_NODES];

// ---------------- packed f32x2 helpers (FFMA2 path) ----------------
static __device__ __forceinline__ unsigned long long pk2(float lo, float hi) {
    unsigned long long r;
    asm("mov.b64 %0, {%1, %2};" : "=l"(r)
        : "r"(__float_as_uint(lo)), "r"(__float_as_uint(hi)));
    return r;
}
static __device__ __forceinline__ void fma2(unsigned long long& d,
                                            unsigned long long a,
                                            unsigned long long b) {
    asm("fma.rn.f32x2 %0, %1, %2, %0;" : "+l"(d) : "l"(a), "l"(b));
}
static __device__ __forceinline__ float2 upk2(unsigned long long v) {
    unsigned int lo, hi;
    asm("mov.b64 {%0, %1}, %2;" : "=r"(lo), "=r"(hi) : "l"(v));
    return make_float2(__uint_as_float(lo), __uint_as_float(hi));
}

// ---------------- CSR build ----------------
__global__ void count_kernel(const int* __restrict__ ei) {
    int b = (blockIdx.x * blockDim.x + threadIdx.x) * 4;
    if (b < N_EDGES) {
        int4 d = *(const int4*)(ei + b);             // 4 dst
        int4 s = *(const int4*)(ei + N_EDGES + b);   // 4 src
        atomicAdd(&g_cnt_row[d.x], 1); atomicAdd(&g_cnt_row[d.y], 1);
        atomicAdd(&g_cnt_row[d.z], 1); atomicAdd(&g_cnt_row[d.w], 1);
        atomicAdd(&g_cnt_col[s.x], 1); atomicAdd(&g_cnt_col[s.y], 1);
        atomicAdd(&g_cnt_col[s.z], 1); atomicAdd(&g_cnt_col[s.w], 1);
    }
}

// block 0: chunked exclusive scan of g_cnt_row -> g_row_ptr
// blocks 1..: dis = rsqrt(deg_col) (0 if deg==0), then RESET g_cnt_col to 0
#define SCAN_CHUNK 49
__global__ __launch_bounds__(1024) void scan_dis_kernel() {
    if (blockIdx.x == 0) {
        __shared__ int wsum[32];
        const int tid = threadIdx.x, lane = tid & 31, wid = tid >> 5;
        const int base = tid * SCAN_CHUNK;
        const int cnt = max(0, min(SCAN_CHUNK, N_NODES - base));
        int s = 0;
        for (int i = 0; i < cnt; ++i) s += g_cnt_row[base + i];
        int x = s;
        #pragma unroll
        for (int off = 1; off < 32; off <<= 1) {
            int t = __shfl_up_sync(0xffffffffu, x, off);
            if (lane >= off) x += t;
        }
        if (lane == 31) wsum[wid] = x;
        __syncthreads();
        if (wid == 0) {
            int w = wsum[lane];
            #pragma unroll
            for (int off = 1; off < 32; off <<= 1) {
                int t = __shfl_up_sync(0xffffffffu, w, off);
                if (lane >= off) w += t;
            }
            wsum[lane] = w;
        }
        __syncthreads();
        int incl = x + ((wid > 0) ? wsum[wid - 1] : 0);
        int run = incl - s;
        if (cnt > 0) {
            g_row_ptr[base] = run;
            for (int i = 0; i < cnt; ++i) {
                run += g_cnt_row[base + i];
                g_row_ptr[base + i + 1] = run;
            }
        }
    } else {
        int i = (blockIdx.x - 1) * 1024 + threadIdx.x;
        if (i < N_NODES) {
            int c = g_cnt_col[i];
            g_dis[i] = (c > 0) ? rsqrtf((float)c) : 0.0f;
            g_cnt_col[i] = 0;   // restore invariant for next replay
        }
    }
}

__global__ void scatter_kernel(const int* __restrict__ ei, const int* __restrict__ et) {
    int b = (blockIdx.x * blockDim.x + threadIdx.x) * 4;
    if (b < N_EDGES) {
        int4 d = *(const int4*)(ei + b);
        int4 s = *(const int4*)(ei + N_EDGES + b);
        int4 t = *(const int4*)(et + b);
        int k;
        k = atomicSub(&g_cnt_row[d.x], 1) - 1;
        g_pk[g_row_ptr[d.x] + k] = (unsigned)s.x | ((unsigned)t.x << 16);
        k = atomicSub(&g_cnt_row[d.y], 1) - 1;
        g_pk[g_row_ptr[d.y] + k] = (unsigned)s.y | ((unsigned)t.y << 16);
        k = atomicSub(&g_cnt_row[d.z], 1) - 1;
        g_pk[g_row_ptr[d.z] + k] = (unsigned)s.z | ((unsigned)t.z << 16);
        k = atomicSub(&g_cnt_row[d.w], 1) - 1;
        g_pk[g_row_ptr[d.w] + k] = (unsigned)s.w | ((unsigned)t.w << 16);
    }
}

// ---------------- fused GEMM (double-buffered B, 4 blocks/SM) ----------------
// X = in@W_in + b ; R[:,z,:] = X@W_rel[z].  smem = As(64x68) + 2 B-buffers.
#define GEMM_SMEM_BYTES ((64 * 68 + 2 * 64 * 64) * 4)  // 50176 B -> 4 blocks/SM

static __device__ __forceinline__ void gemm_tile(const float (*As)[68],
                                                 const float* __restrict__ B,
                                                 int tx, int ty,
                                                 unsigned long long acc[4][2]) {
    #pragma unroll
    for (int i = 0; i < 4; ++i) { acc[i][0] = 0ull; acc[i][1] = 0ull; }
    #pragma unroll
    for (int k = 0; k < 64; ++k) {
        float4 a = *(const float4*)&As[k][ty * 4];
        float4 b = *(const float4*)(B + k * 64 + tx * 4);
        unsigned long long b01 = pk2(b.x, b.y), b23 = pk2(b.z, b.w);
        unsigned long long am;
        am = pk2(a.x, a.x); fma2(acc[0][0], am, b01); fma2(acc[0][1], am, b23);
        am = pk2(a.y, a.y); fma2(acc[1][0], am, b01); fma2(acc[1][1], am, b23);
        am = pk2(a.z, a.z); fma2(acc[2][0], am, b01); fma2(acc[2][1], am, b23);
        am = pk2(a.w, a.w); fma2(acc[3][0], am, b01); fma2(acc[3][1], am, b23);
    }
}

__global__ __launch_bounds__(256, 4) void fused_gemm_kernel(const float* __restrict__ Ain,
                                                            const float* __restrict__ Winw,
                                                            const float* __restrict__ Winb,
                                                            const float* __restrict__ Wrel) {
    extern __shared__ float sm[];
    float (*As)[68] = (float(*)[68])sm;          // [k][m]
    float* B0 = sm + 64 * 68;
    float* B1 = B0 + 4096;
    const int tid = threadIdx.x;
    const int bm  = blockIdx.x * 64;
    const int tx = tid & 15, ty = tid >> 4;

    // W_in -> B0
    #pragma unroll
    for (int i = 0; i < 4; ++i) {
        int s0 = tid + i * 256;
        *(float4*)(B0 + s0 * 4) = *(const float4*)(Winw + s0 * 4);
    }
    // input A tile -> As
    #pragma unroll
    for (int i = 0; i < 4; ++i) {
        int s  = tid + i * 256;
        int r  = s >> 4;
        int kq = s & 15;
        float4 v = make_float4(0.f, 0.f, 0.f, 0.f);
        int grow = bm + r;
        if (grow < N_NODES) v = *(const float4*)(Ain + (size_t)grow * 64 + kq * 4);
        As[kq * 4 + 0][r] = v.x; As[kq * 4 + 1][r] = v.y;
        As[kq * 4 + 2][r] = v.z; As[kq * 4 + 3][r] = v.w;
    }
    // stage Wrel[0] into registers (LDG latency hides behind gemm1)
    float4 st[4];
    #pragma unroll
    for (int i = 0; i < 4; ++i)
        st[i] = *(const float4*)(Wrel + (tid + i * 256) * 4);
    __syncthreads();

    // GEMM 1: X = A @ W_in
    unsigned long long acc[4][2];
    gemm_tile(As, B0, tx, ty, acc);
    __syncthreads();  // all reads of As/B0 complete

    // epilogue: bias, store X, refill As with X
    float4 bv = *(const float4*)(Winb + tx * 4);
    #pragma unroll
    for (int i = 0; i < 4; ++i) {
        int grow = bm + ty * 4 + i;
        float2 c01 = upk2(acc[i][0]);
        float2 c23 = upk2(acc[i][1]);
        float4 x4 = make_float4(c01.x + bv.x, c01.y + bv.y, c23.x + bv.z, c23.y + bv.w);
        As[tx * 4 + 0][ty * 4 + i] = x4.x;
        As[tx * 4 + 1][ty * 4 + i] = x4.y;
        As[tx * 4 + 2][ty * 4 + i] = x4.z;
        As[tx * 4 + 3][ty * 4 + i] = x4.w;
        if (grow < N_NODES)
            *(float4*)(g_X + (size_t)grow * 64 + tx * 4) = x4;
    }
    // B1 <- Wrel0 (from regs); stage Wrel1
    #pragma unroll
    for (int i = 0; i < 4; ++i) *(float4*)(B1 + (tid + i * 256) * 4) = st[i];
    #pragma unroll
    for (int i = 0; i < 4; ++i)
        st[i] = *(const float4*)(Wrel + 4096 + (tid + i * 256) * 4);
    __syncthreads();  // As refill + B1 visible

    // relation GEMMs, ping-pong buffers: z even -> B1, z odd -> B0
    #pragma unroll 1
    for (int z = 0; z < REL; ++z) {
        const float* Bc = (z & 1) ? B0 : B1;
        gemm_tile(As, Bc, tx, ty, acc);
        #pragma unroll
        for (int i = 0; i < 4; ++i) {
            int grow = bm + ty * 4 + i;
            if (grow < N_NODES) {
                float2 c01 = upk2(acc[i][0]);
                float2 c23 = upk2(acc[i][1]);
                float4 v = make_float4(c01.x, c01.y, c23.x, c23.y);
                *(float4*)(g_R + ((size_t)grow * REL + z) * 64 + tx * 4) = v;
            }
        }
        if (z < REL - 1) {
            float* Bn = (z & 1) ? B1 : B0;   // buffer for z+1 (last read at z-1)
            #pragma unroll
            for (int i = 0; i < 4; ++i) *(float4*)(Bn + (tid + i * 256) * 4) = st[i];
            if (z + 2 < REL) {
                #pragma unroll
                for (int i = 0; i < 4; ++i)
                    st[i] = *(const float4*)(Wrel + (size_t)(z + 2) * 4096 + (tid + i * 256) * 4);
            }
            __syncthreads();
        }
    }
}

// ---------------- main edge pass: warp-per-node, 4 edges/iter (MLP x2) ----------------
// raw-exp softmax: segsum >= exp(0)=1 in the reference, so msg = s2/s1 exactly.
__global__ __launch_bounds__(256) void edge_node_kernel(const float* __restrict__ Wout,
                                                        const float* __restrict__ bout,
                                                        float* __restrict__ out) {
    __shared__ float Ws[64 * 64];
    const int tid = threadIdx.x;
    #pragma unroll
    for (int i = 0; i < 16; ++i) Ws[tid + i * 256] = Wout[tid + i * 256];
    __syncthreads();

    const int node = blockIdx.x * 8 + (tid >> 5);
    if (node >= N_NODES) return;
    const int lane = tid & 31;
    const int eg = lane >> 3;        // edge slot 0..3
    const int li = lane & 7;         // channel group: 8*li .. 8*li+7

    const int beg = g_row_ptr[node];
    const int end = g_row_ptr[node + 1];

    float4 s1a = {0,0,0,0}, s1b = {0,0,0,0};
    float4 s2a = {0,0,0,0}, s2b = {0,0,0,0};
    float4 ga  = {0,0,0,0}, gb  = {0,0,0,0};

    for (int i = beg; i < end; i += 4) {
        const int e = i + eg;
        float4 rva = {0,0,0,0}, rvb = {0,0,0,0};
        float4 xva = {0,0,0,0}, xvb = {0,0,0,0};
        float dsc = 0.f, vm = 0.f;
        if (e < end) {
            unsigned p = g_pk[e];
            unsigned src = p & 0xFFFFu;
            unsigned t   = p >> 16;
            dsc = g_dis[src];
            const float* rp = g_R + ((size_t)src * REL + t) * 64 + li * 8;
            rva = *(const float4*)rp;
            rvb = *(const float4*)(rp + 4);
            const float* xp = g_X + (size_t)src * 64 + li * 8;
            xva = *(const float4*)xp;
            xvb = *(const float4*)(xp + 4);
            vm = 1.f;
        }
        ga.x = fmaf(xva.x, dsc, ga.x); ga.y = fmaf(xva.y, dsc, ga.y);
        ga.z = fmaf(xva.z, dsc, ga.z); ga.w = fmaf(xva.w, dsc, ga.w);
        gb.x = fmaf(xvb.x, dsc, gb.x); gb.y = fmaf(xvb.y, dsc, gb.y);
        gb.z = fmaf(xvb.z, dsc, gb.z); gb.w = fmaf(xvb.w, dsc, gb.w);
        float ea0 = __expf(rva.x), ea1 = __expf(rva.y);
        float ea2 = __expf(rva.z), ea3 = __expf(rva.w);
        float eb0 = __expf(rvb.x), eb1 = __expf(rvb.y);
        float eb2 = __expf(rvb.z), eb3 = __expf(rvb.w);
        s1a.x = fmaf(ea0, vm, s1a.x); s2a.x = fmaf(rva.x * ea0, vm, s2a.x);
        s1a.y = fmaf(ea1, vm, s1a.y); s2a.y = fmaf(rva.y * ea1, vm, s2a.y);
        s1a.z = fmaf(ea2, vm, s1a.z); s2a.z = fmaf(rva.z * ea2, vm, s2a.z);
        s1a.w = fmaf(ea3, vm, s1a.w); s2a.w = fmaf(rva.w * ea3, vm, s2a.w);
        s1b.x = fmaf(eb0, vm, s1b.x); s2b.x = fmaf(rvb.x * eb0, vm, s2b.x);
        s1b.y = fmaf(eb1, vm, s1b.y); s2b.y = fmaf(rvb.y * eb1, vm, s2b.y);
        s1b.z = fmaf(eb2, vm, s1b.z); s2b.z = fmaf(rvb.z * eb2, vm, s2b.z);
        s1b.w = fmaf(eb3, vm, s1b.w); s2b.w = fmaf(rvb.w * eb3, vm, s2b.w);
    }

    // reduce across the 4 edge slots (lanes l, l^8, l^16, l^24 share channels)
    #define RED4(v) \
        v.x += __shfl_xor_sync(0xffffffffu, v.x, 8);  \
        v.y += __shfl_xor_sync(0xffffffffu, v.y, 8);  \
        v.z += __shfl_xor_sync(0xffffffffu, v.z, 8);  \
        v.w += __shfl_xor_sync(0xffffffffu, v.w, 8);  \
        v.x += __shfl_xor_sync(0xffffffffu, v.x, 16); \
        v.y += __shfl_xor_sync(0xffffffffu, v.y, 16); \
        v.z += __shfl_xor_sync(0xffffffffu, v.z, 16); \
        v.w += __shfl_xor_sync(0xffffffffu, v.w, 16);
    RED4(s1a) RED4(s1b) RED4(s2a) RED4(s2b) RED4(ga) RED4(gb)
    #undef RED4

    const float dd = g_dis[node];
    float ya[8];
    ya[0] = fmaf(dd, ga.x, 0.5f * fmaxf(s2a.x / (s1a.x + 1e-16f), 0.f));
    ya[1] = fmaf(dd, ga.y, 0.5f * fmaxf(s2a.y / (s1a.y + 1e-16f), 0.f));
    ya[2] = fmaf(dd, ga.z, 0.5f * fmaxf(s2a.z / (s1a.z + 1e-16f), 0.f));
    ya[3] = fmaf(dd, ga.w, 0.5f * fmaxf(s2a.w / (s1a.w + 1e-16f), 0.f));
    ya[4] = fmaf(dd, gb.x, 0.5f * fmaxf(s2b.x / (s1b.x + 1e-16f), 0.f));
    ya[5] = fmaf(dd, gb.y, 0.5f * fmaxf(s2b.y / (s1b.y + 1e-16f), 0.f));
    ya[6] = fmaf(dd, gb.z, 0.5f * fmaxf(s2b.z / (s1b.z + 1e-16f), 0.f));
    ya[7] = fmaf(dd, gb.w, 0.5f * fmaxf(s2b.w / (s1b.w + 1e-16f), 0.f));

    // warp GEMV: out = y @ W_out + b (lane writes channels 2*lane, 2*lane+1)
    float o0 = 0.f, o1 = 0.f;
    #pragma unroll
    for (int sj = 0; sj < 8; ++sj) {
        #pragma unroll
        for (int j = 0; j < 8; ++j) {
            float yv = __shfl_sync(0xffffffffu, ya[j], sj);  // y[sj*8+j]
            float2 w = *(const float2*)(Ws + (sj * 8 + j) * 64 + 2 * lane);
            o0 = fmaf(yv, w.x, o0);
            o1 = fmaf(yv, w.y, o1);
        }
    }
    float2 bb = *(const float2*)(bout + 2 * lane);
    *(float2*)(out + (size_t)node * 64 + 2 * lane) = make_float2(o0 + bb.x, o1 + bb.y);
}

// ---------------- launch ----------------
extern "C" void kernel_launch(void* const* d_in, const int* in_sizes, int n_in,
                              void* d_out, int out_size) {
    const float* cr    = (const float*)d_in[0];
    const float* Winw  = (const float*)d_in[2];
    const float* Winb  = (const float*)d_in[3];
    const float* Wrel  = (const float*)d_in[4];
    const float* Woutw = (const float*)d_in[5];
    const float* Woutb = (const float*)d_in[6];
    const int*   ei    = (const int*)d_in[7];
    const int*   et    = (const int*)d_in[8];
    float* out = (float*)d_out;

    // one-time resource setup (on the correctness call, before capture)
    static cudaStream_t s_side = nullptr;
    static cudaEvent_t  ev_fork = nullptr, ev_join = nullptr;
    static bool s_init = false;
    if (!s_init) {
        cudaStreamCreateWithFlags(&s_side, cudaStreamNonBlocking);
        cudaEventCreateWithFlags(&ev_fork, cudaEventDisableTiming);
        cudaEventCreateWithFlags(&ev_join, cudaEventDisableTiming);
        cudaFuncSetAttribute(fused_gemm_kernel,
                             cudaFuncAttributeMaxDynamicSharedMemorySize,
                             GEMM_SMEM_BYTES);
        s_init = true;
    }

    const int nb_e4 = (N_EDGES / 4 + 255) / 256;
    const int gm    = (N_NODES + 63) / 64;

    // fork: CSR chain on side stream; GEMM concurrently on main stream
    cudaEventRecord(ev_fork, 0);
    cudaStreamWaitEvent(s_side, ev_fork, 0);

    count_kernel<<<nb_e4, 256, 0, s_side>>>(ei);                     // #1
    scan_dis_kernel<<<1 + (N_NODES + 1023) / 1024, 1024, 0, s_side>>>(); // #2
    scatter_kernel<<<nb_e4, 256, 0, s_side>>>(ei, et);               // #3
    cudaEventRecord(ev_join, s_side);

    fused_gemm_kernel<<<gm, 256, GEMM_SMEM_BYTES>>>(cr, Winw, Winb, Wrel); // #4 (profiled)

    // join, then edge pass (needs GEMM results + CSR + dis)
    cudaStreamWaitEvent(0, ev_join, 0);
    edge_node_kernel<<<(N_NODES + 7) / 8, 256>>>(Woutw, Woutb, out); // #5
}

// round 16
// speedup vs baseline: 1.3648x; 1.3648x over previous
#include <cuda_runtime.h>
#include <math.h>

#define N_NODES 50000
#define N_EDGES 800000
#define HID 64
#define REL 5

// ---------------- scratch (static __device__, allowed) ----------------
// No zero_kernel: g_cnt_row returns to 0 after scatter (atomicSub mirrors count's
// atomicAdd); g_cnt_col reset by scan_dis after reading. BSS zero-init covers the
// first run; invariant holds across graph replays.
__device__ float g_X[N_NODES * HID];            // 12.8 MB (UNscaled x)
__device__ float g_R[N_NODES * REL * HID];      // 64 MB
__device__ int   g_cnt_row[N_NODES];
__device__ int   g_cnt_col[N_NODES];
__device__ int   g_row_ptr[N_NODES + 1];
__device__ unsigned g_pk[N_EDGES];              // packed src | (type<<16)
__device__ float g_dis[N_NODES];

// ---------------- packed f32x2 helpers (FFMA2 path) ----------------
static __device__ __forceinline__ unsigned long long pk2(float lo, float hi) {
    unsigned long long r;
    asm("mov.b64 %0, {%1, %2};" : "=l"(r)
        : "r"(__float_as_uint(lo)), "r"(__float_as_uint(hi)));
    return r;
}
static __device__ __forceinline__ void fma2(unsigned long long& d,
                                            unsigned long long a,
                                            unsigned long long b) {
    asm("fma.rn.f32x2 %0, %1, %2, %0;" : "+l"(d) : "l"(a), "l"(b));
}
static __device__ __forceinline__ float2 upk2(unsigned long long v) {
    unsigned int lo, hi;
    asm("mov.b64 {%0, %1}, %2;" : "=r"(lo), "=r"(hi) : "l"(v));
    return make_float2(__uint_as_float(lo), __uint_as_float(hi));
}

// ---------------- CSR build ----------------
__global__ void count_kernel(const int* __restrict__ ei) {
    int b = (blockIdx.x * blockDim.x + threadIdx.x) * 4;
    if (b < N_EDGES) {
        int4 d = *(const int4*)(ei + b);
        int4 s = *(const int4*)(ei + N_EDGES + b);
        atomicAdd(&g_cnt_row[d.x], 1); atomicAdd(&g_cnt_row[d.y], 1);
        atomicAdd(&g_cnt_row[d.z], 1); atomicAdd(&g_cnt_row[d.w], 1);
        atomicAdd(&g_cnt_col[s.x], 1); atomicAdd(&g_cnt_col[s.y], 1);
        atomicAdd(&g_cnt_col[s.z], 1); atomicAdd(&g_cnt_col[s.w], 1);
    }
}

// block 0: chunked exclusive scan of g_cnt_row -> g_row_ptr
// blocks 1..: dis = rsqrt(deg_col) (0 if deg==0), then RESET g_cnt_col
#define SCAN_CHUNK 49
__global__ __launch_bounds__(1024) void scan_dis_kernel() {
    if (blockIdx.x == 0) {
        __shared__ int wsum[32];
        const int tid = threadIdx.x, lane = tid & 31, wid = tid >> 5;
        const int base = tid * SCAN_CHUNK;
        const int cnt = max(0, min(SCAN_CHUNK, N_NODES - base));
        int s = 0;
        for (int i = 0; i < cnt; ++i) s += g_cnt_row[base + i];
        int x = s;
        #pragma unroll
        for (int off = 1; off < 32; off <<= 1) {
            int t = __shfl_up_sync(0xffffffffu, x, off);
            if (lane >= off) x += t;
        }
        if (lane == 31) wsum[wid] = x;
        __syncthreads();
        if (wid == 0) {
            int w = wsum[lane];
            #pragma unroll
            for (int off = 1; off < 32; off <<= 1) {
                int t = __shfl_up_sync(0xffffffffu, w, off);
                if (lane >= off) w += t;
            }
            wsum[lane] = w;
        }
        __syncthreads();
        int incl = x + ((wid > 0) ? wsum[wid - 1] : 0);
        int run = incl - s;
        if (cnt > 0) {
            g_row_ptr[base] = run;
            for (int i = 0; i < cnt; ++i) {
                run += g_cnt_row[base + i];
                g_row_ptr[base + i + 1] = run;
            }
        }
    } else {
        int i = (blockIdx.x - 1) * 1024 + threadIdx.x;
        if (i < N_NODES) {
            int c = g_cnt_col[i];
            g_dis[i] = (c > 0) ? rsqrtf((float)c) : 0.0f;
            g_cnt_col[i] = 0;
        }
    }
}

__global__ void scatter_kernel(const int* __restrict__ ei, const int* __restrict__ et) {
    int b = (blockIdx.x * blockDim.x + threadIdx.x) * 4;
    if (b < N_EDGES) {
        int4 d = *(const int4*)(ei + b);
        int4 s = *(const int4*)(ei + N_EDGES + b);
        int4 t = *(const int4*)(et + b);
        int k;
        k = atomicSub(&g_cnt_row[d.x], 1) - 1;
        g_pk[g_row_ptr[d.x] + k] = (unsigned)s.x | ((unsigned)t.x << 16);
        k = atomicSub(&g_cnt_row[d.y], 1) - 1;
        g_pk[g_row_ptr[d.y] + k] = (unsigned)s.y | ((unsigned)t.y << 16);
        k = atomicSub(&g_cnt_row[d.z], 1) - 1;
        g_pk[g_row_ptr[d.z] + k] = (unsigned)s.z | ((unsigned)t.z << 16);
        k = atomicSub(&g_cnt_row[d.w], 1) - 1;
        g_pk[g_row_ptr[d.w] + k] = (unsigned)s.w | ((unsigned)t.w << 16);
    }
}

// ---------------- fused GEMM: BM=128, per-thread 8m x 4n (LDS traffic x0.75) ----------
// X = in@W_in + b ; R[:,z,:] = X@W_rel[z].
#define AS_LD 132                                    // row stride (floats), 16B-aligned
#define GEMM_SMEM_BYTES ((64 * AS_LD + 64 * 64) * 4) // 50176 B -> 4 blocks/SM

__global__ __launch_bounds__(256) void fused_gemm_kernel(const float* __restrict__ Ain,
                                                         const float* __restrict__ Winw,
                                                         const float* __restrict__ Winb,
                                                         const float* __restrict__ Wrel) {
    extern __shared__ float sm[];
    float* As = sm;                    // [k][m], 64 x AS_LD
    float* Bs = sm + 64 * AS_LD;       // [k][n], 64 x 64
    const int tid = threadIdx.x;
    const int bm  = blockIdx.x * 128;
    const int tx = tid & 15;           // n quad: cols tx*4..+3
    const int ty = tid >> 4;           // m oct:  rows ty*8..+7

    // load A tile (128 rows x 64 cols = 2048 float4), W_in -> Bs (1024 float4)
    #pragma unroll
    for (int i = 0; i < 8; ++i) {
        int s  = tid + i * 256;
        int r  = s >> 4;               // row 0..127
        int kq = s & 15;
        float4 v = make_float4(0.f, 0.f, 0.f, 0.f);
        int grow = bm + r;
        if (grow < N_NODES) v = *(const float4*)(Ain + (size_t)grow * 64 + kq * 4);
        As[(kq * 4 + 0) * AS_LD + r] = v.x;
        As[(kq * 4 + 1) * AS_LD + r] = v.y;
        As[(kq * 4 + 2) * AS_LD + r] = v.z;
        As[(kq * 4 + 3) * AS_LD + r] = v.w;
    }
    #pragma unroll
    for (int i = 0; i < 4; ++i) {
        int s0 = tid + i * 256;
        *(float4*)(Bs + s0 * 4) = *(const float4*)(Winw + s0 * 4);
    }
    __syncthreads();

    unsigned long long acc[8][2];

    // ---- GEMM 1: X = A @ W_in ----
    #pragma unroll
    for (int i = 0; i < 8; ++i) { acc[i][0] = 0ull; acc[i][1] = 0ull; }
    #pragma unroll
    for (int k = 0; k < 64; ++k) {
        float4 aLo = *(const float4*)(As + k * AS_LD + ty * 8);
        float4 aHi = *(const float4*)(As + k * AS_LD + ty * 8 + 4);
        float4 b   = *(const float4*)(Bs + k * 64 + tx * 4);
        unsigned long long b01 = pk2(b.x, b.y), b23 = pk2(b.z, b.w);
        unsigned long long am;
        am = pk2(aLo.x, aLo.x); fma2(acc[0][0], am, b01); fma2(acc[0][1], am, b23);
        am = pk2(aLo.y, aLo.y); fma2(acc[1][0], am, b01); fma2(acc[1][1], am, b23);
        am = pk2(aLo.z, aLo.z); fma2(acc[2][0], am, b01); fma2(acc[2][1], am, b23);
        am = pk2(aLo.w, aLo.w); fma2(acc[3][0], am, b01); fma2(acc[3][1], am, b23);
        am = pk2(aHi.x, aHi.x); fma2(acc[4][0], am, b01); fma2(acc[4][1], am, b23);
        am = pk2(aHi.y, aHi.y); fma2(acc[5][0], am, b01); fma2(acc[5][1], am, b23);
        am = pk2(aHi.z, aHi.z); fma2(acc[6][0], am, b01); fma2(acc[6][1], am, b23);
        am = pk2(aHi.w, aHi.w); fma2(acc[7][0], am, b01); fma2(acc[7][1], am, b23);
    }
    __syncthreads();  // all reads of As/Bs complete

    // epilogue: bias, store X, refill As with X
    float4 bv = *(const float4*)(Winb + tx * 4);
    #pragma unroll
    for (int i = 0; i < 8; ++i) {
        int row  = ty * 8 + i;
        int grow = bm + row;
        float2 c01 = upk2(acc[i][0]);
        float2 c23 = upk2(acc[i][1]);
        float4 x4 = make_float4(c01.x + bv.x, c01.y + bv.y, c23.x + bv.z, c23.y + bv.w);
        As[(tx * 4 + 0) * AS_LD + row] = x4.x;
        As[(tx * 4 + 1) * AS_LD + row] = x4.y;
        As[(tx * 4 + 2) * AS_LD + row] = x4.z;
        As[(tx * 4 + 3) * AS_LD + row] = x4.w;
        if (grow < N_NODES)
            *(float4*)(g_X + (size_t)grow * 64 + tx * 4) = x4;
    }

    // ---- 5 relation GEMMs: R[:,z,:] = X @ W_rel[z] ----
    #pragma unroll 1
    for (int z = 0; z < REL; ++z) {
        __syncthreads();  // previous Bs readers done (z=0: As refill visible too)
        #pragma unroll
        for (int i = 0; i < 4; ++i) {
            int s0 = tid + i * 256;
            *(float4*)(Bs + s0 * 4) = *(const float4*)(Wrel + (size_t)z * 4096 + s0 * 4);
        }
        __syncthreads();
        #pragma unroll
        for (int i = 0; i < 8; ++i) { acc[i][0] = 0ull; acc[i][1] = 0ull; }
        #pragma unroll
        for (int k = 0; k < 64; ++k) {
            float4 aLo = *(const float4*)(As + k * AS_LD + ty * 8);
            float4 aHi = *(const float4*)(As + k * AS_LD + ty * 8 + 4);
            float4 b   = *(const float4*)(Bs + k * 64 + tx * 4);
            unsigned long long b01 = pk2(b.x, b.y), b23 = pk2(b.z, b.w);
            unsigned long long am;
            am = pk2(aLo.x, aLo.x); fma2(acc[0][0], am, b01); fma2(acc[0][1], am, b23);
            am = pk2(aLo.y, aLo.y); fma2(acc[1][0], am, b01); fma2(acc[1][1], am, b23);
            am = pk2(aLo.z, aLo.z); fma2(acc[2][0], am, b01); fma2(acc[2][1], am, b23);
            am = pk2(aLo.w, aLo.w); fma2(acc[3][0], am, b01); fma2(acc[3][1], am, b23);
            am = pk2(aHi.x, aHi.x); fma2(acc[4][0], am, b01); fma2(acc[4][1], am, b23);
            am = pk2(aHi.y, aHi.y); fma2(acc[5][0], am, b01); fma2(acc[5][1], am, b23);
            am = pk2(aHi.z, aHi.z); fma2(acc[6][0], am, b01); fma2(acc[6][1], am, b23);
            am = pk2(aHi.w, aHi.w); fma2(acc[7][0], am, b01); fma2(acc[7][1], am, b23);
        }
        #pragma unroll
        for (int i = 0; i < 8; ++i) {
            int grow = bm + ty * 8 + i;
            if (grow < N_NODES) {
                float2 c01 = upk2(acc[i][0]);
                float2 c23 = upk2(acc[i][1]);
                float4 v = make_float4(c01.x, c01.y, c23.x, c23.y);
                *(float4*)(g_R + ((size_t)grow * REL + z) * 64 + tx * 4) = v;
            }
        }
    }
}

// ---------------- main edge pass: warp-per-node, 2 edges/iter (R9-proven) ----------
// raw-exp softmax: segsum >= exp(0)=1 in the reference, so msg = s2/s1 exactly.
__global__ __launch_bounds__(256) void edge_node_kernel(const float* __restrict__ Wout,
                                                        const float* __restrict__ bout,
                                                        float* __restrict__ out) {
    __shared__ float Ws[64 * 64];
    const int tid = threadIdx.x;
    #pragma unroll
    for (int i = 0; i < 16; ++i) Ws[tid + i * 256] = Wout[tid + i * 256];
    __syncthreads();

    const int node = blockIdx.x * 8 + (tid >> 5);
    if (node >= N_NODES) return;
    const int lane = tid & 31;
    const int half = lane >> 4;
    const int li   = lane & 15;

    const int beg = g_row_ptr[node];
    const int end = g_row_ptr[node + 1];

    float4 s1 = make_float4(0.f, 0.f, 0.f, 0.f);
    float4 s2 = make_float4(0.f, 0.f, 0.f, 0.f);
    float4 g  = make_float4(0.f, 0.f, 0.f, 0.f);

    for (int i = beg; i < end; i += 2) {
        const int e = i + half;
        float4 rv = make_float4(0.f, 0.f, 0.f, 0.f);
        float4 xv = make_float4(0.f, 0.f, 0.f, 0.f);
        float dsc = 0.f, vm = 0.f;
        if (e < end) {
            unsigned p = g_pk[e];
            unsigned src = p & 0xFFFFu;
            unsigned t   = p >> 16;
            dsc = g_dis[src];
            rv = *(const float4*)(g_R + ((size_t)src * REL + t) * 64 + li * 4);
            xv = *(const float4*)(g_X + (size_t)src * 64 + li * 4);
            vm = 1.f;
        }
        g.x = fmaf(xv.x, dsc, g.x); g.y = fmaf(xv.y, dsc, g.y);
        g.z = fmaf(xv.z, dsc, g.z); g.w = fmaf(xv.w, dsc, g.w);
        float e0 = __expf(rv.x), e1 = __expf(rv.y);
        float e2 = __expf(rv.z), e3 = __expf(rv.w);
        s1.x = fmaf(e0, vm, s1.x); s2.x = fmaf(rv.x * e0, vm, s2.x);
        s1.y = fmaf(e1, vm, s1.y); s2.y = fmaf(rv.y * e1, vm, s2.y);
        s1.z = fmaf(e2, vm, s1.z); s2.z = fmaf(rv.z * e2, vm, s2.z);
        s1.w = fmaf(e3, vm, s1.w); s2.w = fmaf(rv.w * e3, vm, s2.w);
    }

    s1.x += __shfl_xor_sync(0xffffffffu, s1.x, 16);
    s1.y += __shfl_xor_sync(0xffffffffu, s1.y, 16);
    s1.z += __shfl_xor_sync(0xffffffffu, s1.z, 16);
    s1.w += __shfl_xor_sync(0xffffffffu, s1.w, 16);
    s2.x += __shfl_xor_sync(0xffffffffu, s2.x, 16);
    s2.y += __shfl_xor_sync(0xffffffffu, s2.y, 16);
    s2.z += __shfl_xor_sync(0xffffffffu, s2.z, 16);
    s2.w += __shfl_xor_sync(0xffffffffu, s2.w, 16);
    g.x  += __shfl_xor_sync(0xffffffffu, g.x, 16);
    g.y  += __shfl_xor_sync(0xffffffffu, g.y, 16);
    g.z  += __shfl_xor_sync(0xffffffffu, g.z, 16);
    g.w  += __shfl_xor_sync(0xffffffffu, g.w, 16);

    const float dd = g_dis[node];
    float4 y;
    y.x = fmaf(dd, g.x, 0.5f * fmaxf(s2.x / (s1.x + 1e-16f), 0.f));
    y.y = fmaf(dd, g.y, 0.5f * fmaxf(s2.y / (s1.y + 1e-16f), 0.f));
    y.z = fmaf(dd, g.z, 0.5f * fmaxf(s2.z / (s1.z + 1e-16f), 0.f));
    y.w = fmaf(dd, g.w, 0.5f * fmaxf(s2.w / (s1.w + 1e-16f), 0.f));

    float o0 = 0.f, o1 = 0.f;
    #pragma unroll
    for (int jj = 0; jj < 16; ++jj) {
        float ya = __shfl_sync(0xffffffffu, y.x, jj);
        float yb = __shfl_sync(0xffffffffu, y.y, jj);
        float yc = __shfl_sync(0xffffffffu, y.z, jj);
        float yd = __shfl_sync(0xffffffffu, y.w, jj);
        float2 w0 = *(const float2*)(Ws + (4 * jj + 0) * 64 + 2 * lane);
        float2 w1 = *(const float2*)(Ws + (4 * jj + 1) * 64 + 2 * lane);
        float2 w2 = *(const float2*)(Ws + (4 * jj + 2) * 64 + 2 * lane);
        float2 w3 = *(const float2*)(Ws + (4 * jj + 3) * 64 + 2 * lane);
        o0 = fmaf(ya, w0.x, o0); o1 = fmaf(ya, w0.y, o1);
        o0 = fmaf(yb, w1.x, o0); o1 = fmaf(yb, w1.y, o1);
        o0 = fmaf(yc, w2.x, o0); o1 = fmaf(yc, w2.y, o1);
        o0 = fmaf(yd, w3.x, o0); o1 = fmaf(yd, w3.y, o1);
    }
    float2 bb = *(const float2*)(bout + 2 * lane);
    *(float2*)(out + (size_t)node * 64 + 2 * lane) = make_float2(o0 + bb.x, o1 + bb.y);
}

// ---------------- launch (serial, single stream) ----------------
extern "C" void kernel_launch(void* const* d_in, const int* in_sizes, int n_in,
                              void* d_out, int out_size) {
    const float* cr    = (const float*)d_in[0];
    const float* Winw  = (const float*)d_in[2];
    const float* Winb  = (const float*)d_in[3];
    const float* Wrel  = (const float*)d_in[4];
    const float* Woutw = (const float*)d_in[5];
    const float* Woutb = (const float*)d_in[6];
    const int*   ei    = (const int*)d_in[7];
    const int*   et    = (const int*)d_in[8];
    float* out = (float*)d_out;

    static bool s_init = false;
    if (!s_init) {
        cudaFuncSetAttribute(fused_gemm_kernel,
                             cudaFuncAttributeMaxDynamicSharedMemorySize,
                             GEMM_SMEM_BYTES);
        s_init = true;
    }

    const int nb_e4 = (N_EDGES / 4 + 255) / 256;
    const int gm    = (N_NODES + 127) / 128;   // 391 blocks

    count_kernel<<<nb_e4, 256>>>(ei);                                  // #1
    scan_dis_kernel<<<1 + (N_NODES + 1023) / 1024, 1024>>>();          // #2
    scatter_kernel<<<nb_e4, 256>>>(ei, et);                            // #3
    fused_gemm_kernel<<<gm, 256, GEMM_SMEM_BYTES>>>(cr, Winw, Winb, Wrel); // #4 (profiled)
    edge_node_kernel<<<(N_NODES + 7) / 8, 256>>>(Woutw, Woutb, out);   // #5
}